// round 4
// baseline (speedup 1.0000x reference)
#include <cuda_runtime.h>
#include <cuda_bf16.h>

// RWKV single-token inference, fp32, HBM-bound matvec pipeline.
// D=1024, H=4096, L=24, V=50277.

#define D   1024
#define HD  4096
#define NL  24
#define NV  50277
#define WARPS 8
#define NT  256

// Inter-kernel scratch (device globals: allocation-free).
__device__ float g_x[D];
__device__ float g_rwkv[D];
__device__ float g_kk[HD];
__device__ float g_r2[D];
__device__ float g_state_scratch[NL * 5 * D];

__device__ __forceinline__ float sum4(float4 a) { return a.x + a.y + a.z + a.w; }

// Block-wide sum for 256 threads. sred must hold WARPS floats.
__device__ __forceinline__ float block_sum256(float v, float* sred) {
    __syncthreads();  // protect sred reuse
#pragma unroll
    for (int o = 16; o > 0; o >>= 1) v += __shfl_xor_sync(0xffffffffu, v, o);
    int warp = threadIdx.x >> 5, lane = threadIdx.x & 31;
    if (lane == 0) sred[warp] = v;
    __syncthreads();
    float t = 0.f;
#pragma unroll
    for (int w = 0; w < WARPS; w++) t += sred[w];
    return t;
}

__device__ __forceinline__ float warp_sum(float s) {
#pragma unroll
    for (int o = 16; o > 0; o >>= 1) s += __shfl_xor_sync(0xffffffffu, s, o);
    return s;
}

// Warp dot of one 1024-wide weight row with a shared-memory vector.
__device__ __forceinline__ float dot1024(const float* __restrict__ w,
                                         const float* __restrict__ xs, int lane) {
    const float4* w4 = (const float4*)w;
    const float4* x4 = (const float4*)xs;
    float s = 0.f;
#pragma unroll
    for (int j = 0; j < 8; j++) {
        float4 a = w4[lane + 32 * j];
        float4 b = x4[lane + 32 * j];
        s = fmaf(a.x, b.x, s); s = fmaf(a.y, b.y, s);
        s = fmaf(a.z, b.z, s); s = fmaf(a.w, b.w, s);
    }
    return warp_sum(s);
}

// ---------------------------------------------------------------------------
// Kernel 0: x = LN(emb[token], ln0)
// ---------------------------------------------------------------------------
__global__ __launch_bounds__(NT) void k_embed(const int* __restrict__ token,
                                              const float* __restrict__ emb,
                                              const float* __restrict__ w,
                                              const float* __restrict__ b) {
    __shared__ float sred[WARPS];
    int t = threadIdx.x;
    const float4* row = (const float4*)(emb + (size_t)token[0] * D);
    float4 xv = row[t];
    float mu = block_sum256(sum4(xv), sred) * (1.f / D);
    float dx = xv.x - mu, dy = xv.y - mu, dz = xv.z - mu, dw = xv.w - mu;
    float var = block_sum256(dx * dx + dy * dy + dz * dz + dw * dw, sred) * (1.f / D);
    float rstd = rsqrtf(var + 1e-5f);
    float4 wv = ((const float4*)w)[t];
    float4 bv = ((const float4*)b)[t];
    float4 o;
    o.x = dx * rstd * wv.x + bv.x;
    o.y = dy * rstd * wv.y + bv.y;
    o.z = dz * rstd * wv.z + bv.z;
    o.w = dw * rstd * wv.w + bv.w;
    ((float4*)g_x)[t] = o;
}

// ---------------------------------------------------------------------------
// Kernel A: time mixing. LN1(x) -> xk/xv/xr, three DxD matvecs, WKV, r*wkv.
// Writes g_rwkv and state rows 1 (xn), 2 (aa2), 3 (bb2), 4 (qq2).
// grid = D/WARPS = 128 blocks
// ---------------------------------------------------------------------------
__global__ __launch_bounds__(NT) void k_timemix(
    int l, const float* __restrict__ state_in,
    const float* __restrict__ ln1_w, const float* __restrict__ ln1_b,
    const float* __restrict__ kw, const float* __restrict__ vw,
    const float* __restrict__ rw,
    const float* __restrict__ mk, const float* __restrict__ mv,
    const float* __restrict__ mr,
    const float* __restrict__ tf, const float* __restrict__ td,
    float* __restrict__ state_out) {
    __shared__ float sred[WARPS];
    __shared__ float s_xk[D], s_xv[D], s_xr[D];
    int t = threadIdx.x;

    // LN1 (redundant per block; x is 4KB, L2-resident)
    float4 xv4 = ((const float4*)g_x)[t];
    float mu = block_sum256(sum4(xv4), sred) * (1.f / D);
    float xa[4]; *(float4*)xa = xv4;
    float d0 = xa[0] - mu, d1 = xa[1] - mu, d2 = xa[2] - mu, d3 = xa[3] - mu;
    float var = block_sum256(d0 * d0 + d1 * d1 + d2 * d2 + d3 * d3, sred) * (1.f / D);
    float rstd = rsqrtf(var + 1e-5f);

    const float* lw = ln1_w + (size_t)l * D;
    const float* lb = ln1_b + (size_t)l * D;
    const float* sx = state_in + (size_t)l * 5 * D + D;  // row 1 = sx_att
    float wa[4], ba[4], mka[4], mva[4], mra[4], sxa[4], da[4] = {d0, d1, d2, d3};
    *(float4*)wa  = ((const float4*)lw)[t];
    *(float4*)ba  = ((const float4*)lb)[t];
    *(float4*)mka = ((const float4*)(mk + (size_t)l * D))[t];
    *(float4*)mva = ((const float4*)(mv + (size_t)l * D))[t];
    *(float4*)mra = ((const float4*)(mr + (size_t)l * D))[t];
    *(float4*)sxa = ((const float4*)sx)[t];
    int base = 4 * t;
#pragma unroll
    for (int c = 0; c < 4; c++) {
        float xn = da[c] * rstd * wa[c] + ba[c];
        s_xk[base + c] = xn * mka[c] + sxa[c] * (1.f - mka[c]);
        s_xv[base + c] = xn * mva[c] + sxa[c] * (1.f - mva[c]);
        s_xr[base + c] = xn * mra[c] + sxa[c] * (1.f - mra[c]);
        if (blockIdx.x == 0)  // state row 1 = xn
            state_out[(size_t)l * 5 * D + D + base + c] = xn;
    }
    __syncthreads();

    int warp = t >> 5, lane = t & 31;
    int r = blockIdx.x * WARPS + warp;
    size_t off = (size_t)l * D * D + (size_t)r * D;
    float sk = dot1024(kw + off, s_xk, lane);
    float sv = dot1024(vw + off, s_xv, lane);
    float sr = dot1024(rw + off, s_xr, lane);

    if (lane == 0) {
        size_t sbase = (size_t)l * 5 * D;
        float aa = state_in[sbase + 2 * D + r];
        float bb = state_in[sbase + 3 * D + r];
        float pp = state_in[sbase + 4 * D + r];
        float tfv = tf[(size_t)l * D + r];
        float tdv = td[(size_t)l * D + r];
        float k = sk, v = sv;
        float rs = 1.f / (1.f + expf(-sr));

        float ww = tfv + k;
        float qq = fmaxf(pp, ww);
        float e1 = expf(pp - qq);
        float e2 = expf(ww - qq);
        float wkv = (e1 * aa + e2 * v) / (e1 * bb + e2);
        g_rwkv[r] = rs * wkv;

        float ww2 = pp + tdv;
        float qq2 = fmaxf(ww2, k);
        float e1b = expf(ww2 - qq2);
        float e2b = expf(k - qq2);
        state_out[sbase + 2 * D + r] = e1b * aa + e2b * v;  // aa2
        state_out[sbase + 3 * D + r] = e1b * bb + e2b;      // bb2
        state_out[sbase + 4 * D + r] = qq2;                 // qq2
    }
}

// ---------------------------------------------------------------------------
// Kernel B: x += ow @ rwkv.  grid = 128
// ---------------------------------------------------------------------------
__global__ __launch_bounds__(NT) void k_attout(int l, const float* __restrict__ ow) {
    __shared__ float s_v[D];
    int t = threadIdx.x;
    ((float4*)s_v)[t] = ((const float4*)g_rwkv)[t];
    __syncthreads();
    int warp = t >> 5, lane = t & 31;
    int r = blockIdx.x * WARPS + warp;
    float s = dot1024(ow + (size_t)l * D * D + (size_t)r * D, s_v, lane);
    if (lane == 0) g_x[r] += s;
}

// ---------------------------------------------------------------------------
// Kernel C: channel mix part 1. LN2(x) -> xk2/xr2; kk = relu(fkw@xk2)^2 (H rows),
// r2 = sigmoid(frw@xr2) (D rows). Writes state row 0 (xn2).
// grid = (HD + D) / WARPS = 640
// ---------------------------------------------------------------------------
__global__ __launch_bounds__(NT) void k_chan1(
    int l, const float* __restrict__ state_in,
    const float* __restrict__ ln2_w, const float* __restrict__ ln2_b,
    const float* __restrict__ fkw, const float* __restrict__ frw,
    const float* __restrict__ fmk, const float* __restrict__ fmr,
    float* __restrict__ state_out) {
    __shared__ float sred[WARPS];
    __shared__ float s_xk[D], s_xr[D];
    int t = threadIdx.x;

    float4 xv4 = ((const float4*)g_x)[t];
    float mu = block_sum256(sum4(xv4), sred) * (1.f / D);
    float xa[4]; *(float4*)xa = xv4;
    float d0 = xa[0] - mu, d1 = xa[1] - mu, d2 = xa[2] - mu, d3 = xa[3] - mu;
    float var = block_sum256(d0 * d0 + d1 * d1 + d2 * d2 + d3 * d3, sred) * (1.f / D);
    float rstd = rsqrtf(var + 1e-5f);

    const float* sx = state_in + (size_t)l * 5 * D;  // row 0 = sx_ffn
    float wa[4], ba[4], mka[4], mra[4], sxa[4], da[4] = {d0, d1, d2, d3};
    *(float4*)wa  = ((const float4*)(ln2_w + (size_t)l * D))[t];
    *(float4*)ba  = ((const float4*)(ln2_b + (size_t)l * D))[t];
    *(float4*)mka = ((const float4*)(fmk + (size_t)l * D))[t];
    *(float4*)mra = ((const float4*)(fmr + (size_t)l * D))[t];
    *(float4*)sxa = ((const float4*)sx)[t];
    int base = 4 * t;
#pragma unroll
    for (int c = 0; c < 4; c++) {
        float xn = da[c] * rstd * wa[c] + ba[c];
        s_xk[base + c] = xn * mka[c] + sxa[c] * (1.f - mka[c]);
        s_xr[base + c] = xn * mra[c] + sxa[c] * (1.f - mra[c]);
        if (blockIdx.x == 0)  // state row 0 = xn2
            state_out[(size_t)l * 5 * D + base + c] = xn;
    }
    __syncthreads();

    int warp = t >> 5, lane = t & 31;
    int gr = blockIdx.x * WARPS + warp;
    if (gr < HD) {
        float s = dot1024(fkw + (size_t)l * HD * D + (size_t)gr * D, s_xk, lane);
        if (lane == 0) {
            float rl = fmaxf(s, 0.f);
            g_kk[gr] = rl * rl;
        }
    } else {
        int r = gr - HD;
        float s = dot1024(frw + (size_t)l * D * D + (size_t)r * D, s_xr, lane);
        if (lane == 0) g_r2[r] = 1.f / (1.f + expf(-s));
    }
}

// ---------------------------------------------------------------------------
// Kernel D: x += r2 * (fvw @ kk).  Row dot over H=4096.  grid = 128
// ---------------------------------------------------------------------------
__global__ __launch_bounds__(NT) void k_chan2(int l, const float* __restrict__ fvw) {
    __shared__ float s_kk[HD];  // 16 KB
    int t = threadIdx.x;
#pragma unroll
    for (int j = 0; j < 4; j++)
        ((float4*)s_kk)[t + NT * j] = ((const float4*)g_kk)[t + NT * j];
    __syncthreads();
    int warp = t >> 5, lane = t & 31;
    int r = blockIdx.x * WARPS + warp;
    const float4* w4 = (const float4*)(fvw + (size_t)l * D * HD + (size_t)r * HD);
    const float4* x4 = (const float4*)s_kk;
    float s = 0.f;
#pragma unroll
    for (int j = 0; j < 32; j++) {
        float4 a = w4[lane + 32 * j];
        float4 b = x4[lane + 32 * j];
        s = fmaf(a.x, b.x, s); s = fmaf(a.y, b.y, s);
        s = fmaf(a.z, b.z, s); s = fmaf(a.w, b.w, s);
    }
    s = warp_sum(s);
    if (lane == 0) g_x[r] += g_r2[r] * s;
}

// ---------------------------------------------------------------------------
// Head: logits = head @ LN(x, lnout).  grid = ceil(V/WARPS)
// ---------------------------------------------------------------------------
__global__ __launch_bounds__(NT) void k_head(const float* __restrict__ lnw,
                                             const float* __restrict__ lnb,
                                             const float* __restrict__ head,
                                             float* __restrict__ logits) {
    __shared__ float sred[WARPS];
    __shared__ float s_x[D];
    int t = threadIdx.x;
    float4 xv4 = ((const float4*)g_x)[t];
    float mu = block_sum256(sum4(xv4), sred) * (1.f / D);
    float xa[4]; *(float4*)xa = xv4;
    float d0 = xa[0] - mu, d1 = xa[1] - mu, d2 = xa[2] - mu, d3 = xa[3] - mu;
    float var = block_sum256(d0 * d0 + d1 * d1 + d2 * d2 + d3 * d3, sred) * (1.f / D);
    float rstd = rsqrtf(var + 1e-5f);
    float wa[4], ba[4], da[4] = {d0, d1, d2, d3};
    *(float4*)wa = ((const float4*)lnw)[t];
    *(float4*)ba = ((const float4*)lnb)[t];
    int base = 4 * t;
#pragma unroll
    for (int c = 0; c < 4; c++) s_x[base + c] = da[c] * rstd * wa[c] + ba[c];
    __syncthreads();

    int warp = t >> 5, lane = t & 31;
    int v = blockIdx.x * WARPS + warp;
    if (v < NV) {
        float s = dot1024(head + (size_t)v * D, s_x, lane);
        if (lane == 0) logits[v] = s;
    }
}

// ---------------------------------------------------------------------------
extern "C" void kernel_launch(void* const* d_in, const int* in_sizes, int n_in,
                              void* d_out, int out_size) {
    const int*   token     = (const int*)d_in[0];
    const float* state     = (const float*)d_in[1];
    const float* emb       = (const float*)d_in[2];
    const float* ln0_w     = (const float*)d_in[3];
    const float* ln0_b     = (const float*)d_in[4];
    const float* ln1_w     = (const float*)d_in[5];
    const float* ln1_b     = (const float*)d_in[6];
    const float* ln2_w     = (const float*)d_in[7];
    const float* ln2_b     = (const float*)d_in[8];
    const float* att_key   = (const float*)d_in[9];
    const float* att_value = (const float*)d_in[10];
    const float* att_recep = (const float*)d_in[11];
    const float* att_out   = (const float*)d_in[12];
    const float* tm_k      = (const float*)d_in[13];
    const float* tm_v      = (const float*)d_in[14];
    const float* tm_r      = (const float*)d_in[15];
    const float* t_first   = (const float*)d_in[16];
    const float* t_decay   = (const float*)d_in[17];
    const float* ffn_key   = (const float*)d_in[18];
    const float* ffn_value = (const float*)d_in[19];
    const float* ffn_recep = (const float*)d_in[20];
    const float* ffn_tm_k  = (const float*)d_in[21];
    const float* ffn_tm_r  = (const float*)d_in[22];
    const float* lnout_w   = (const float*)d_in[23];
    const float* lnout_b   = (const float*)d_in[24];
    const float* head      = (const float*)d_in[25];

    float* out = (float*)d_out;
    float* logits = out;
    float* state_out;
    if (out_size >= NV + NL * 5 * D) {
        state_out = out + NV;
    } else {
        // Output only holds logits; route state writes to scratch.
        void* p = nullptr;
        cudaGetSymbolAddress(&p, g_state_scratch);
        state_out = (float*)p;
    }

    k_embed<<<1, NT>>>(token, emb, ln0_w, ln0_b);
    for (int l = 0; l < NL; l++) {
        k_timemix<<<D / WARPS, NT>>>(l, state, ln1_w, ln1_b,
                                     att_key, att_value, att_recep,
                                     tm_k, tm_v, tm_r, t_first, t_decay,
                                     state_out);
        k_attout<<<D / WARPS, NT>>>(l, att_out);
        k_chan1<<<(HD + D) / WARPS, NT>>>(l, state, ln2_w, ln2_b,
                                          ffn_key, ffn_recep,
                                          ffn_tm_k, ffn_tm_r, state_out);
        k_chan2<<<D / WARPS, NT>>>(l, ffn_value);
    }
    k_head<<<(NV + WARPS - 1) / WARPS, NT>>>(lnout_w, lnout_b, head, logits);
}

// round 5
// speedup vs baseline: 1.0053x; 1.0053x over previous
#include <cuda_runtime.h>
#include <cuda_bf16.h>

// RWKV single-token inference, fp32, HBM-bound matvec pipeline.
// D=1024, H=4096, L=24, V=50277.

#define D   1024
#define HD  4096
#define NL  24
#define NV  50277
#define WARPS 8
#define NT  256

// Inter-kernel scratch (device globals: allocation-free).
__device__ float g_x[D];
__device__ float g_rwkv[D];
__device__ float g_kk[HD];
__device__ float g_r2[D];
__device__ float g_state_scratch[NL * 5 * D];

__device__ __forceinline__ float sum4(float4 a) { return a.x + a.y + a.z + a.w; }

// Block-wide sum for 256 threads. sred must hold WARPS floats.
__device__ __forceinline__ float block_sum256(float v, float* sred) {
    __syncthreads();  // protect sred reuse
#pragma unroll
    for (int o = 16; o > 0; o >>= 1) v += __shfl_xor_sync(0xffffffffu, v, o);
    int warp = threadIdx.x >> 5, lane = threadIdx.x & 31;
    if (lane == 0) sred[warp] = v;
    __syncthreads();
    float t = 0.f;
#pragma unroll
    for (int w = 0; w < WARPS; w++) t += sred[w];
    return t;
}

__device__ __forceinline__ float warp_sum(float s) {
#pragma unroll
    for (int o = 16; o > 0; o >>= 1) s += __shfl_xor_sync(0xffffffffu, s, o);
    return s;
}

// Warp dot of one 1024-wide weight row with a shared-memory vector.
__device__ __forceinline__ float dot1024(const float* __restrict__ w,
                                         const float* __restrict__ xs, int lane) {
    const float4* w4 = (const float4*)w;
    const float4* x4 = (const float4*)xs;
    float s = 0.f;
#pragma unroll
    for (int j = 0; j < 8; j++) {
        float4 a = w4[lane + 32 * j];
        float4 b = x4[lane + 32 * j];
        s = fmaf(a.x, b.x, s); s = fmaf(a.y, b.y, s);
        s = fmaf(a.z, b.z, s); s = fmaf(a.w, b.w, s);
    }
    return warp_sum(s);
}

// ---------------------------------------------------------------------------
// Kernel 0: x = LN(emb[token], ln0)
// ---------------------------------------------------------------------------
__global__ __launch_bounds__(NT) void k_embed(const int* __restrict__ token,
                                              const float* __restrict__ emb,
                                              const float* __restrict__ w,
                                              const float* __restrict__ b) {
    __shared__ float sred[WARPS];
    int t = threadIdx.x;
    const float4* row = (const float4*)(emb + (size_t)token[0] * D);
    float4 xv = row[t];
    float mu = block_sum256(sum4(xv), sred) * (1.f / D);
    float dx = xv.x - mu, dy = xv.y - mu, dz = xv.z - mu, dw = xv.w - mu;
    float var = block_sum256(dx * dx + dy * dy + dz * dz + dw * dw, sred) * (1.f / D);
    float rstd = rsqrtf(var + 1e-5f);
    float4 wv = ((const float4*)w)[t];
    float4 bv = ((const float4*)b)[t];
    float4 o;
    o.x = dx * rstd * wv.x + bv.x;
    o.y = dy * rstd * wv.y + bv.y;
    o.z = dz * rstd * wv.z + bv.z;
    o.w = dw * rstd * wv.w + bv.w;
    ((float4*)g_x)[t] = o;
}

// ---------------------------------------------------------------------------
// Kernel A: time mixing. LN1(x) -> xk/xv/xr, three DxD matvecs, WKV, r*wkv.
// Writes g_rwkv and state rows 1 (xn), 2 (aa2), 3 (bb2), 4 (qq2).
// grid = D/WARPS = 128 blocks
// ---------------------------------------------------------------------------
__global__ __launch_bounds__(NT) void k_timemix(
    int l, const float* __restrict__ state_in,
    const float* __restrict__ ln1_w, const float* __restrict__ ln1_b,
    const float* __restrict__ kw, const float* __restrict__ vw,
    const float* __restrict__ rw,
    const float* __restrict__ mk, const float* __restrict__ mv,
    const float* __restrict__ mr,
    const float* __restrict__ tf, const float* __restrict__ td,
    float* __restrict__ state_out) {
    __shared__ float sred[WARPS];
    __shared__ float s_xk[D], s_xv[D], s_xr[D];
    int t = threadIdx.x;

    // LN1 (redundant per block; x is 4KB, L2-resident)
    float4 xv4 = ((const float4*)g_x)[t];
    float mu = block_sum256(sum4(xv4), sred) * (1.f / D);
    float xa[4]; *(float4*)xa = xv4;
    float d0 = xa[0] - mu, d1 = xa[1] - mu, d2 = xa[2] - mu, d3 = xa[3] - mu;
    float var = block_sum256(d0 * d0 + d1 * d1 + d2 * d2 + d3 * d3, sred) * (1.f / D);
    float rstd = rsqrtf(var + 1e-5f);

    const float* lw = ln1_w + (size_t)l * D;
    const float* lb = ln1_b + (size_t)l * D;
    const float* sx = state_in + (size_t)l * 5 * D + D;  // row 1 = sx_att
    float wa[4], ba[4], mka[4], mva[4], mra[4], sxa[4], da[4] = {d0, d1, d2, d3};
    *(float4*)wa  = ((const float4*)lw)[t];
    *(float4*)ba  = ((const float4*)lb)[t];
    *(float4*)mka = ((const float4*)(mk + (size_t)l * D))[t];
    *(float4*)mva = ((const float4*)(mv + (size_t)l * D))[t];
    *(float4*)mra = ((const float4*)(mr + (size_t)l * D))[t];
    *(float4*)sxa = ((const float4*)sx)[t];
    int base = 4 * t;
#pragma unroll
    for (int c = 0; c < 4; c++) {
        float xn = da[c] * rstd * wa[c] + ba[c];
        s_xk[base + c] = xn * mka[c] + sxa[c] * (1.f - mka[c]);
        s_xv[base + c] = xn * mva[c] + sxa[c] * (1.f - mva[c]);
        s_xr[base + c] = xn * mra[c] + sxa[c] * (1.f - mra[c]);
        if (blockIdx.x == 0)  // state row 1 = xn
            state_out[(size_t)l * 5 * D + D + base + c] = xn;
    }
    __syncthreads();

    int warp = t >> 5, lane = t & 31;
    int r = blockIdx.x * WARPS + warp;
    size_t off = (size_t)l * D * D + (size_t)r * D;
    float sk = dot1024(kw + off, s_xk, lane);
    float sv = dot1024(vw + off, s_xv, lane);
    float sr = dot1024(rw + off, s_xr, lane);

    if (lane == 0) {
        size_t sbase = (size_t)l * 5 * D;
        float aa = state_in[sbase + 2 * D + r];
        float bb = state_in[sbase + 3 * D + r];
        float pp = state_in[sbase + 4 * D + r];
        float tfv = tf[(size_t)l * D + r];
        float tdv = td[(size_t)l * D + r];
        float k = sk, v = sv;
        float rs = 1.f / (1.f + expf(-sr));

        float ww = tfv + k;
        float qq = fmaxf(pp, ww);
        float e1 = expf(pp - qq);
        float e2 = expf(ww - qq);
        float wkv = (e1 * aa + e2 * v) / (e1 * bb + e2);
        g_rwkv[r] = rs * wkv;

        float ww2 = pp + tdv;
        float qq2 = fmaxf(ww2, k);
        float e1b = expf(ww2 - qq2);
        float e2b = expf(k - qq2);
        state_out[sbase + 2 * D + r] = e1b * aa + e2b * v;  // aa2
        state_out[sbase + 3 * D + r] = e1b * bb + e2b;      // bb2
        state_out[sbase + 4 * D + r] = qq2;                 // qq2
    }
}

// ---------------------------------------------------------------------------
// Kernel B: x += ow @ rwkv.  grid = 128
// ---------------------------------------------------------------------------
__global__ __launch_bounds__(NT) void k_attout(int l, const float* __restrict__ ow) {
    __shared__ float s_v[D];
    int t = threadIdx.x;
    ((float4*)s_v)[t] = ((const float4*)g_rwkv)[t];
    __syncthreads();
    int warp = t >> 5, lane = t & 31;
    int r = blockIdx.x * WARPS + warp;
    float s = dot1024(ow + (size_t)l * D * D + (size_t)r * D, s_v, lane);
    if (lane == 0) g_x[r] += s;
}

// ---------------------------------------------------------------------------
// Kernel C: channel mix part 1. LN2(x) -> xk2/xr2; kk = relu(fkw@xk2)^2 (H rows),
// r2 = sigmoid(frw@xr2) (D rows). Writes state row 0 (xn2).
// grid = (HD + D) / WARPS = 640
// ---------------------------------------------------------------------------
__global__ __launch_bounds__(NT) void k_chan1(
    int l, const float* __restrict__ state_in,
    const float* __restrict__ ln2_w, const float* __restrict__ ln2_b,
    const float* __restrict__ fkw, const float* __restrict__ frw,
    const float* __restrict__ fmk, const float* __restrict__ fmr,
    float* __restrict__ state_out) {
    __shared__ float sred[WARPS];
    __shared__ float s_xk[D], s_xr[D];
    int t = threadIdx.x;

    float4 xv4 = ((const float4*)g_x)[t];
    float mu = block_sum256(sum4(xv4), sred) * (1.f / D);
    float xa[4]; *(float4*)xa = xv4;
    float d0 = xa[0] - mu, d1 = xa[1] - mu, d2 = xa[2] - mu, d3 = xa[3] - mu;
    float var = block_sum256(d0 * d0 + d1 * d1 + d2 * d2 + d3 * d3, sred) * (1.f / D);
    float rstd = rsqrtf(var + 1e-5f);

    const float* sx = state_in + (size_t)l * 5 * D;  // row 0 = sx_ffn
    float wa[4], ba[4], mka[4], mra[4], sxa[4], da[4] = {d0, d1, d2, d3};
    *(float4*)wa  = ((const float4*)(ln2_w + (size_t)l * D))[t];
    *(float4*)ba  = ((const float4*)(ln2_b + (size_t)l * D))[t];
    *(float4*)mka = ((const float4*)(fmk + (size_t)l * D))[t];
    *(float4*)mra = ((const float4*)(fmr + (size_t)l * D))[t];
    *(float4*)sxa = ((const float4*)sx)[t];
    int base = 4 * t;
#pragma unroll
    for (int c = 0; c < 4; c++) {
        float xn = da[c] * rstd * wa[c] + ba[c];
        s_xk[base + c] = xn * mka[c] + sxa[c] * (1.f - mka[c]);
        s_xr[base + c] = xn * mra[c] + sxa[c] * (1.f - mra[c]);
        if (blockIdx.x == 0)  // state row 0 = xn2
            state_out[(size_t)l * 5 * D + base + c] = xn;
    }
    __syncthreads();

    int warp = t >> 5, lane = t & 31;
    int gr = blockIdx.x * WARPS + warp;
    if (gr < HD) {
        float s = dot1024(fkw + (size_t)l * HD * D + (size_t)gr * D, s_xk, lane);
        if (lane == 0) {
            float rl = fmaxf(s, 0.f);
            g_kk[gr] = rl * rl;
        }
    } else {
        int r = gr - HD;
        float s = dot1024(frw + (size_t)l * D * D + (size_t)r * D, s_xr, lane);
        if (lane == 0) g_r2[r] = 1.f / (1.f + expf(-s));
    }
}

// ---------------------------------------------------------------------------
// Kernel D: x += r2 * (fvw @ kk).  Row dot over H=4096.  grid = 128
// ---------------------------------------------------------------------------
__global__ __launch_bounds__(NT) void k_chan2(int l, const float* __restrict__ fvw) {
    __shared__ float s_kk[HD];  // 16 KB
    int t = threadIdx.x;
#pragma unroll
    for (int j = 0; j < 4; j++)
        ((float4*)s_kk)[t + NT * j] = ((const float4*)g_kk)[t + NT * j];
    __syncthreads();
    int warp = t >> 5, lane = t & 31;
    int r = blockIdx.x * WARPS + warp;
    const float4* w4 = (const float4*)(fvw + (size_t)l * D * HD + (size_t)r * HD);
    const float4* x4 = (const float4*)s_kk;
    float s = 0.f;
#pragma unroll
    for (int j = 0; j < 32; j++) {
        float4 a = w4[lane + 32 * j];
        float4 b = x4[lane + 32 * j];
        s = fmaf(a.x, b.x, s); s = fmaf(a.y, b.y, s);
        s = fmaf(a.z, b.z, s); s = fmaf(a.w, b.w, s);
    }
    s = warp_sum(s);
    if (lane == 0) g_x[r] += g_r2[r] * s;
}

// ---------------------------------------------------------------------------
// Head: logits = head @ LN(x, lnout).  grid = ceil(V/WARPS)
// ---------------------------------------------------------------------------
__global__ __launch_bounds__(NT) void k_head(const float* __restrict__ lnw,
                                             const float* __restrict__ lnb,
                                             const float* __restrict__ head,
                                             float* __restrict__ logits) {
    __shared__ float sred[WARPS];
    __shared__ float s_x[D];
    int t = threadIdx.x;
    float4 xv4 = ((const float4*)g_x)[t];
    float mu = block_sum256(sum4(xv4), sred) * (1.f / D);
    float xa[4]; *(float4*)xa = xv4;
    float d0 = xa[0] - mu, d1 = xa[1] - mu, d2 = xa[2] - mu, d3 = xa[3] - mu;
    float var = block_sum256(d0 * d0 + d1 * d1 + d2 * d2 + d3 * d3, sred) * (1.f / D);
    float rstd = rsqrtf(var + 1e-5f);
    float wa[4], ba[4], da[4] = {d0, d1, d2, d3};
    *(float4*)wa = ((const float4*)lnw)[t];
    *(float4*)ba = ((const float4*)lnb)[t];
    int base = 4 * t;
#pragma unroll
    for (int c = 0; c < 4; c++) s_x[base + c] = da[c] * rstd * wa[c] + ba[c];
    __syncthreads();

    int warp = t >> 5, lane = t & 31;
    int v = blockIdx.x * WARPS + warp;
    if (v < NV) {
        float s = dot1024(head + (size_t)v * D, s_x, lane);
        if (lane == 0) logits[v] = s;
    }
}

// ---------------------------------------------------------------------------
extern "C" void kernel_launch(void* const* d_in, const int* in_sizes, int n_in,
                              void* d_out, int out_size) {
    const int*   token     = (const int*)d_in[0];
    const float* state     = (const float*)d_in[1];
    const float* emb       = (const float*)d_in[2];
    const float* ln0_w     = (const float*)d_in[3];
    const float* ln0_b     = (const float*)d_in[4];
    const float* ln1_w     = (const float*)d_in[5];
    const float* ln1_b     = (const float*)d_in[6];
    const float* ln2_w     = (const float*)d_in[7];
    const float* ln2_b     = (const float*)d_in[8];
    const float* att_key   = (const float*)d_in[9];
    const float* att_value = (const float*)d_in[10];
    const float* att_recep = (const float*)d_in[11];
    const float* att_out   = (const float*)d_in[12];
    const float* tm_k      = (const float*)d_in[13];
    const float* tm_v      = (const float*)d_in[14];
    const float* tm_r      = (const float*)d_in[15];
    const float* t_first   = (const float*)d_in[16];
    const float* t_decay   = (const float*)d_in[17];
    const float* ffn_key   = (const float*)d_in[18];
    const float* ffn_value = (const float*)d_in[19];
    const float* ffn_recep = (const float*)d_in[20];
    const float* ffn_tm_k  = (const float*)d_in[21];
    const float* ffn_tm_r  = (const float*)d_in[22];
    const float* lnout_w   = (const float*)d_in[23];
    const float* lnout_b   = (const float*)d_in[24];
    const float* head      = (const float*)d_in[25];

    float* out = (float*)d_out;
    float* logits = out;
    float* state_out;
    if (out_size >= NV + NL * 5 * D) {
        state_out = out + NV;
    } else {
        // Output only holds logits; route state writes to scratch.
        void* p = nullptr;
        cudaGetSymbolAddress(&p, g_state_scratch);
        state_out = (float*)p;
    }

    k_embed<<<1, NT>>>(token, emb, ln0_w, ln0_b);
    for (int l = 0; l < NL; l++) {
        k_timemix<<<D / WARPS, NT>>>(l, state, ln1_w, ln1_b,
                                     att_key, att_value, att_recep,
                                     tm_k, tm_v, tm_r, t_first, t_decay,
                                     state_out);
        k_attout<<<D / WARPS, NT>>>(l, att_out);
        k_chan1<<<(HD + D) / WARPS, NT>>>(l, state, ln2_w, ln2_b,
                                          ffn_key, ffn_recep,
                                          ffn_tm_k, ffn_tm_r, state_out);
        k_chan2<<<D / WARPS, NT>>>(l, ffn_value);
    }
    k_head<<<(NV + WARPS - 1) / WARPS, NT>>>(lnout_w, lnout_b, head, logits);
}

// round 6
// speedup vs baseline: 1.0612x; 1.0556x over previous
#include <cuda_runtime.h>
#include <cuda_bf16.h>

// RWKV single-token inference, fp32. Latency-hiding version:
// weight-row loads are issued into registers BEFORE the LN prologue so the
// DRAM latency overlaps the block-reduction work.
// D=1024, H=4096, L=24, V=50277.

#define D   1024
#define HD  4096
#define NL  24
#define NV  50277

// Inter-kernel scratch (device globals: allocation-free).
__device__ float g_x[D];
__device__ float g_rwkv[D];
__device__ float g_kk[HD];
__device__ float g_r2[D];
__device__ float g_state_scratch[NL * 5 * D];

__device__ __forceinline__ float sum4(float4 a) { return a.x + a.y + a.z + a.w; }

__device__ __forceinline__ float warp_sum(float s) {
#pragma unroll
    for (int o = 16; o > 0; o >>= 1) s += __shfl_xor_sync(0xffffffffu, s, o);
    return s;
}

// Block sum, 256 threads (8 warps).
__device__ __forceinline__ float block_sum256(float v, float* sred) {
    __syncthreads();
    v = warp_sum(v);
    int warp = threadIdx.x >> 5, lane = threadIdx.x & 31;
    if (lane == 0) sred[warp] = v;
    __syncthreads();
    float t = 0.f;
#pragma unroll
    for (int w = 0; w < 8; w++) t += sred[w];
    return t;
}

// Block sum, 128 threads (4 warps).
__device__ __forceinline__ float block_sum128(float v, float* sred) {
    __syncthreads();
    v = warp_sum(v);
    int warp = threadIdx.x >> 5, lane = threadIdx.x & 31;
    if (lane == 0) sred[warp] = v;
    __syncthreads();
    float t = 0.f;
#pragma unroll
    for (int w = 0; w < 4; w++) t += sred[w];
    return t;
}

// ---------------------------------------------------------------------------
// Kernel 0: x = LN(emb[token], ln0).  1 block, 256 threads.
// ---------------------------------------------------------------------------
__global__ __launch_bounds__(256) void k_embed(const int* __restrict__ token,
                                               const float* __restrict__ emb,
                                               const float* __restrict__ w,
                                               const float* __restrict__ b) {
    __shared__ float sred[8];
    int t = threadIdx.x;
    const float4* row = (const float4*)(emb + (size_t)token[0] * D);
    float4 xv = row[t];
    float mu = block_sum256(sum4(xv), sred) * (1.f / D);
    float dx = xv.x - mu, dy = xv.y - mu, dz = xv.z - mu, dw = xv.w - mu;
    float var = block_sum256(dx * dx + dy * dy + dz * dz + dw * dw, sred) * (1.f / D);
    float rstd = rsqrtf(var + 1e-5f);
    float4 wv = ((const float4*)w)[t];
    float4 bv = ((const float4*)b)[t];
    float4 o;
    o.x = dx * rstd * wv.x + bv.x;
    o.y = dy * rstd * wv.y + bv.y;
    o.z = dz * rstd * wv.z + bv.z;
    o.w = dw * rstd * wv.w + bv.w;
    ((float4*)g_x)[t] = o;
}

// ---------------------------------------------------------------------------
// Kernel A: time mixing.  128 threads (4 warps), 1 row/warp, grid 256.
// Weight rows for k/v/r preloaded into 96 registers before the LN prologue.
// ---------------------------------------------------------------------------
__global__ __launch_bounds__(128) void k_timemix(
    int l, const float* __restrict__ state_in,
    const float* __restrict__ ln1_w, const float* __restrict__ ln1_b,
    const float* __restrict__ kw, const float* __restrict__ vw,
    const float* __restrict__ rw,
    const float* __restrict__ mk, const float* __restrict__ mv,
    const float* __restrict__ mr,
    const float* __restrict__ tf, const float* __restrict__ td,
    float* __restrict__ state_out) {
    __shared__ float sred[4];
    __shared__ float s_xk[D], s_xv[D], s_xr[D];
    int t = threadIdx.x, warp = t >> 5, lane = t & 31;
    int r = blockIdx.x * 4 + warp;
    size_t off = (size_t)l * D * D + (size_t)r * D;

    // ---- Phase 0: issue all weight loads (DRAM) up front ----
    const float4* kr = (const float4*)(kw + off);
    const float4* vr = (const float4*)(vw + off);
    const float4* rr = (const float4*)(rw + off);
    float4 wkreg[8], wvreg[8], wrreg[8];
#pragma unroll
    for (int j = 0; j < 8; j++) wkreg[j] = kr[lane + 32 * j];
#pragma unroll
    for (int j = 0; j < 8; j++) wvreg[j] = vr[lane + 32 * j];
#pragma unroll
    for (int j = 0; j < 8; j++) wrreg[j] = rr[lane + 32 * j];

    // ---- Phase 1: LN1 prologue (hidden under the weight loads) ----
    float4 x0 = ((const float4*)g_x)[2 * t];
    float4 x1 = ((const float4*)g_x)[2 * t + 1];
    float mu = block_sum128(sum4(x0) + sum4(x1), sred) * (1.f / D);
    float xa[8]; *(float4*)xa = x0; *(float4*)(xa + 4) = x1;
    float da[8], vs = 0.f;
#pragma unroll
    for (int c = 0; c < 8; c++) { da[c] = xa[c] - mu; vs += da[c] * da[c]; }
    float var = block_sum128(vs, sred) * (1.f / D);
    float rstd = rsqrtf(var + 1e-5f);

    size_t lo = (size_t)l * D;
    float wa[8], ba[8], mka[8], mva[8], mra[8], sxa[8];
    *(float4*)wa      = ((const float4*)(ln1_w + lo))[2 * t];
    *(float4*)(wa+4)  = ((const float4*)(ln1_w + lo))[2 * t + 1];
    *(float4*)ba      = ((const float4*)(ln1_b + lo))[2 * t];
    *(float4*)(ba+4)  = ((const float4*)(ln1_b + lo))[2 * t + 1];
    *(float4*)mka     = ((const float4*)(mk + lo))[2 * t];
    *(float4*)(mka+4) = ((const float4*)(mk + lo))[2 * t + 1];
    *(float4*)mva     = ((const float4*)(mv + lo))[2 * t];
    *(float4*)(mva+4) = ((const float4*)(mv + lo))[2 * t + 1];
    *(float4*)mra     = ((const float4*)(mr + lo))[2 * t];
    *(float4*)(mra+4) = ((const float4*)(mr + lo))[2 * t + 1];
    const float* sx = state_in + (size_t)l * 5 * D + D;  // row 1 = sx_att
    *(float4*)sxa     = ((const float4*)sx)[2 * t];
    *(float4*)(sxa+4) = ((const float4*)sx)[2 * t + 1];

    int base = 8 * t;
#pragma unroll
    for (int c = 0; c < 8; c++) {
        float xn = da[c] * rstd * wa[c] + ba[c];
        s_xk[base + c] = xn * mka[c] + sxa[c] * (1.f - mka[c]);
        s_xv[base + c] = xn * mva[c] + sxa[c] * (1.f - mva[c]);
        s_xr[base + c] = xn * mra[c] + sxa[c] * (1.f - mra[c]);
        if (blockIdx.x == 0)  // state row 1 = xn (block 0 covers all of D)
            state_out[(size_t)l * 5 * D + D + base + c] = xn;
    }
    __syncthreads();

    // ---- Phase 2: consume preloaded weights ----
    const float4* xk4 = (const float4*)s_xk;
    const float4* xv4 = (const float4*)s_xv;
    const float4* xr4 = (const float4*)s_xr;
    float sk = 0.f, sv = 0.f, sr = 0.f;
#pragma unroll
    for (int j = 0; j < 8; j++) {
        float4 bk = xk4[lane + 32 * j];
        sk = fmaf(wkreg[j].x, bk.x, sk); sk = fmaf(wkreg[j].y, bk.y, sk);
        sk = fmaf(wkreg[j].z, bk.z, sk); sk = fmaf(wkreg[j].w, bk.w, sk);
        float4 bv = xv4[lane + 32 * j];
        sv = fmaf(wvreg[j].x, bv.x, sv); sv = fmaf(wvreg[j].y, bv.y, sv);
        sv = fmaf(wvreg[j].z, bv.z, sv); sv = fmaf(wvreg[j].w, bv.w, sv);
        float4 br = xr4[lane + 32 * j];
        sr = fmaf(wrreg[j].x, br.x, sr); sr = fmaf(wrreg[j].y, br.y, sr);
        sr = fmaf(wrreg[j].z, br.z, sr); sr = fmaf(wrreg[j].w, br.w, sr);
    }
    sk = warp_sum(sk); sv = warp_sum(sv); sr = warp_sum(sr);

    if (lane == 0) {
        size_t sbase = (size_t)l * 5 * D;
        float aa = state_in[sbase + 2 * D + r];
        float bb = state_in[sbase + 3 * D + r];
        float pp = state_in[sbase + 4 * D + r];
        float tfv = tf[lo + r];
        float tdv = td[lo + r];
        float k = sk, v = sv;
        float rs = 1.f / (1.f + expf(-sr));

        float ww = tfv + k;
        float qq = fmaxf(pp, ww);
        float e1 = expf(pp - qq);
        float e2 = expf(ww - qq);
        float wkv = (e1 * aa + e2 * v) / (e1 * bb + e2);
        g_rwkv[r] = rs * wkv;

        float ww2 = pp + tdv;
        float qq2 = fmaxf(ww2, k);
        float e1b = expf(ww2 - qq2);
        float e2b = expf(k - qq2);
        state_out[sbase + 2 * D + r] = e1b * aa + e2b * v;  // aa2
        state_out[sbase + 3 * D + r] = e1b * bb + e2b;      // bb2
        state_out[sbase + 4 * D + r] = qq2;                 // qq2
    }
}

// ---------------------------------------------------------------------------
// Kernel B: x += ow @ rwkv.  128 threads, 1 row/warp, grid 256.
// ---------------------------------------------------------------------------
__global__ __launch_bounds__(128) void k_attout(int l, const float* __restrict__ ow) {
    __shared__ float s_v[D];
    int t = threadIdx.x, warp = t >> 5, lane = t & 31;
    int r = blockIdx.x * 4 + warp;
    const float4* wrow = (const float4*)(ow + (size_t)l * D * D + (size_t)r * D);
    float4 wreg[8];
#pragma unroll
    for (int j = 0; j < 8; j++) wreg[j] = wrow[lane + 32 * j];

    ((float4*)s_v)[2 * t]     = ((const float4*)g_rwkv)[2 * t];
    ((float4*)s_v)[2 * t + 1] = ((const float4*)g_rwkv)[2 * t + 1];
    __syncthreads();

    const float4* x4 = (const float4*)s_v;
    float s = 0.f;
#pragma unroll
    for (int j = 0; j < 8; j++) {
        float4 b = x4[lane + 32 * j];
        s = fmaf(wreg[j].x, b.x, s); s = fmaf(wreg[j].y, b.y, s);
        s = fmaf(wreg[j].z, b.z, s); s = fmaf(wreg[j].w, b.w, s);
    }
    s = warp_sum(s);
    if (lane == 0) g_x[r] += s;
}

// ---------------------------------------------------------------------------
// Kernel C: channel mix part 1.  256 threads (8 warps), grid 640.
// kk = relu(fkw@xk2)^2 (rows 0..4095), r2 = sigmoid(frw@xr2) (rows 4096..5119).
// ---------------------------------------------------------------------------
__global__ __launch_bounds__(256) void k_chan1(
    int l, const float* __restrict__ state_in,
    const float* __restrict__ ln2_w, const float* __restrict__ ln2_b,
    const float* __restrict__ fkw, const float* __restrict__ frw,
    const float* __restrict__ fmk, const float* __restrict__ fmr,
    float* __restrict__ state_out) {
    __shared__ float sred[8];
    __shared__ float s_xk[D], s_xr[D];
    int t = threadIdx.x, warp = t >> 5, lane = t & 31;
    int gr = blockIdx.x * 8 + warp;

    // ---- Phase 0: preload this warp's weight row ----
    const float4* wrow = (gr < HD)
        ? (const float4*)(fkw + (size_t)l * HD * D + (size_t)gr * D)
        : (const float4*)(frw + (size_t)l * D * D + (size_t)(gr - HD) * D);
    float4 wreg[8];
#pragma unroll
    for (int j = 0; j < 8; j++) wreg[j] = wrow[lane + 32 * j];

    // ---- Phase 1: LN2 prologue ----
    float4 xv4 = ((const float4*)g_x)[t];
    float mu = block_sum256(sum4(xv4), sred) * (1.f / D);
    float xa[4]; *(float4*)xa = xv4;
    float da[4], vs = 0.f;
#pragma unroll
    for (int c = 0; c < 4; c++) { da[c] = xa[c] - mu; vs += da[c] * da[c]; }
    float var = block_sum256(vs, sred) * (1.f / D);
    float rstd = rsqrtf(var + 1e-5f);

    size_t lo = (size_t)l * D;
    const float* sx = state_in + (size_t)l * 5 * D;  // row 0 = sx_ffn
    float wa[4], ba[4], mka[4], mra[4], sxa[4];
    *(float4*)wa  = ((const float4*)(ln2_w + lo))[t];
    *(float4*)ba  = ((const float4*)(ln2_b + lo))[t];
    *(float4*)mka = ((const float4*)(fmk + lo))[t];
    *(float4*)mra = ((const float4*)(fmr + lo))[t];
    *(float4*)sxa = ((const float4*)sx)[t];
    int base = 4 * t;
#pragma unroll
    for (int c = 0; c < 4; c++) {
        float xn = da[c] * rstd * wa[c] + ba[c];
        s_xk[base + c] = xn * mka[c] + sxa[c] * (1.f - mka[c]);
        s_xr[base + c] = xn * mra[c] + sxa[c] * (1.f - mra[c]);
        if (blockIdx.x == 0)  // state row 0 = xn2
            state_out[(size_t)l * 5 * D + base + c] = xn;
    }
    __syncthreads();

    // ---- Phase 2: consume ----
    const float4* xs4 = (gr < HD) ? (const float4*)s_xk : (const float4*)s_xr;
    float s = 0.f;
#pragma unroll
    for (int j = 0; j < 8; j++) {
        float4 b = xs4[lane + 32 * j];
        s = fmaf(wreg[j].x, b.x, s); s = fmaf(wreg[j].y, b.y, s);
        s = fmaf(wreg[j].z, b.z, s); s = fmaf(wreg[j].w, b.w, s);
    }
    s = warp_sum(s);
    if (lane == 0) {
        if (gr < HD) {
            float rl = fmaxf(s, 0.f);
            g_kk[gr] = rl * rl;
        } else {
            g_r2[gr - HD] = 1.f / (1.f + expf(-s));
        }
    }
}

// ---------------------------------------------------------------------------
// Kernel D: x += r2 * (fvw @ kk).  128 threads (4 warps), 2 rows/block,
// each row split across a warp pair (2048 elems = 16 preloaded float4/thread).
// grid = 512.  kk read directly from L2 (written by k_chan1).
// ---------------------------------------------------------------------------
__global__ __launch_bounds__(128) void k_chan2(int l, const float* __restrict__ fvw) {
    __shared__ float part[4];
    int t = threadIdx.x, warp = t >> 5, lane = t & 31;
    int r = blockIdx.x * 2 + (warp >> 1);
    int half = warp & 1;

    const float4* w4 = (const float4*)(fvw + (size_t)l * D * HD + (size_t)r * HD
                                       + (size_t)half * 2048);
    float4 wreg[16];
#pragma unroll
    for (int j = 0; j < 16; j++) wreg[j] = w4[lane + 32 * j];

    const float4* kk4 = (const float4*)g_kk + half * 512;
    float s = 0.f;
#pragma unroll
    for (int j = 0; j < 16; j++) {
        float4 b = kk4[lane + 32 * j];
        s = fmaf(wreg[j].x, b.x, s); s = fmaf(wreg[j].y, b.y, s);
        s = fmaf(wreg[j].z, b.z, s); s = fmaf(wreg[j].w, b.w, s);
    }
    s = warp_sum(s);
    if (lane == 0) part[warp] = s;
    __syncthreads();
    if (t < 2) {
        int row = blockIdx.x * 2 + t;
        float tot = part[2 * t] + part[2 * t + 1];
        g_x[row] += g_r2[row] * tot;
    }
}

// ---------------------------------------------------------------------------
// Head: logits = head @ LN(x, lnout).  256 threads, 1 row/warp, grid 6285.
// ---------------------------------------------------------------------------
__global__ __launch_bounds__(256) void k_head(const float* __restrict__ lnw,
                                              const float* __restrict__ lnb,
                                              const float* __restrict__ head,
                                              float* __restrict__ logits) {
    __shared__ float sred[8];
    __shared__ float s_x[D];
    int t = threadIdx.x, warp = t >> 5, lane = t & 31;
    int v = blockIdx.x * 8 + warp;

    // ---- Phase 0: preload head row ----
    float4 wreg[8];
    if (v < NV) {
        const float4* wrow = (const float4*)(head + (size_t)v * D);
#pragma unroll
        for (int j = 0; j < 8; j++) wreg[j] = wrow[lane + 32 * j];
    }

    // ---- Phase 1: LN prologue ----
    float4 xv4 = ((const float4*)g_x)[t];
    float mu = block_sum256(sum4(xv4), sred) * (1.f / D);
    float xa[4]; *(float4*)xa = xv4;
    float da[4], vs = 0.f;
#pragma unroll
    for (int c = 0; c < 4; c++) { da[c] = xa[c] - mu; vs += da[c] * da[c]; }
    float var = block_sum256(vs, sred) * (1.f / D);
    float rstd = rsqrtf(var + 1e-5f);
    float wa[4], ba[4];
    *(float4*)wa = ((const float4*)lnw)[t];
    *(float4*)ba = ((const float4*)lnb)[t];
    int base = 4 * t;
#pragma unroll
    for (int c = 0; c < 4; c++) s_x[base + c] = da[c] * rstd * wa[c] + ba[c];
    __syncthreads();

    // ---- Phase 2 ----
    if (v < NV) {
        const float4* x4 = (const float4*)s_x;
        float s = 0.f;
#pragma unroll
        for (int j = 0; j < 8; j++) {
            float4 b = x4[lane + 32 * j];
            s = fmaf(wreg[j].x, b.x, s); s = fmaf(wreg[j].y, b.y, s);
            s = fmaf(wreg[j].z, b.z, s); s = fmaf(wreg[j].w, b.w, s);
        }
        s = warp_sum(s);
        if (lane == 0) logits[v] = s;
    }
}

// ---------------------------------------------------------------------------
extern "C" void kernel_launch(void* const* d_in, const int* in_sizes, int n_in,
                              void* d_out, int out_size) {
    const int*   token     = (const int*)d_in[0];
    const float* state     = (const float*)d_in[1];
    const float* emb       = (const float*)d_in[2];
    const float* ln0_w     = (const float*)d_in[3];
    const float* ln0_b     = (const float*)d_in[4];
    const float* ln1_w     = (const float*)d_in[5];
    const float* ln1_b     = (const float*)d_in[6];
    const float* ln2_w     = (const float*)d_in[7];
    const float* ln2_b     = (const float*)d_in[8];
    const float* att_key   = (const float*)d_in[9];
    const float* att_value = (const float*)d_in[10];
    const float* att_recep = (const float*)d_in[11];
    const float* att_out   = (const float*)d_in[12];
    const float* tm_k      = (const float*)d_in[13];
    const float* tm_v      = (const float*)d_in[14];
    const float* tm_r      = (const float*)d_in[15];
    const float* t_first   = (const float*)d_in[16];
    const float* t_decay   = (const float*)d_in[17];
    const float* ffn_key   = (const float*)d_in[18];
    const float* ffn_value = (const float*)d_in[19];
    const float* ffn_recep = (const float*)d_in[20];
    const float* ffn_tm_k  = (const float*)d_in[21];
    const float* ffn_tm_r  = (const float*)d_in[22];
    const float* lnout_w   = (const float*)d_in[23];
    const float* lnout_b   = (const float*)d_in[24];
    const float* head      = (const float*)d_in[25];

    float* out = (float*)d_out;
    float* logits = out;
    float* state_out;
    if (out_size >= NV + NL * 5 * D) {
        state_out = out + NV;
    } else {
        void* p = nullptr;
        cudaGetSymbolAddress(&p, g_state_scratch);
        state_out = (float*)p;
    }

    k_embed<<<1, 256>>>(token, emb, ln0_w, ln0_b);
    for (int l = 0; l < NL; l++) {
        k_timemix<<<256, 128>>>(l, state, ln1_w, ln1_b,
                                att_key, att_value, att_recep,
                                tm_k, tm_v, tm_r, t_first, t_decay,
                                state_out);
        k_attout<<<256, 128>>>(l, att_out);
        k_chan1<<<(HD + D) / 8, 256>>>(l, state, ln2_w, ln2_b,
                                       ffn_key, ffn_recep,
                                       ffn_tm_k, ffn_tm_r, state_out);
        k_chan2<<<512, 128>>>(l, ffn_value);
    }
    k_head<<<(NV + 7) / 8, 256>>>(lnout_w, lnout_b, head, logits);
}

// round 7
// speedup vs baseline: 1.0880x; 1.0253x over previous
#include <cuda_runtime.h>
#include <cuda_bf16.h>

// RWKV single-token inference, fp32 — single persistent kernel with a
// grid-wide software barrier. 148 blocks x 256 threads (1 CTA/SM, co-resident).
// Weight-row loads for the NEXT phase are issued BEFORE each barrier so the
// DRAM stream never drains across phase boundaries.
// D=1024, H=4096, L=24, V=50277.

#define D    1024
#define HD   4096
#define NL   24
#define NV   50277
#define GRID 148
#define NTH  256
#define NWARP 8
#define TOTW (GRID * NWARP)   // 1184 warps

// Device-global scratch (allocation-free).
__device__ float g_x[D];
__device__ float g_rwkv[D];
__device__ float g_kk[HD];
__device__ float g_r2[D];
__device__ float g_state_scratch[NL * 5 * D];
__device__ unsigned g_count;   // zero-init; returns to 0 after every barrier
__device__ unsigned g_gen;     // monotonically increasing generation

__device__ __forceinline__ float warp_sum(float s) {
#pragma unroll
    for (int o = 16; o > 0; o >>= 1) s += __shfl_xor_sync(0xffffffffu, s, o);
    return s;
}

__device__ __forceinline__ float block_sum256(float v, float* sred) {
    __syncthreads();
    v = warp_sum(v);
    int warp = threadIdx.x >> 5, lane = threadIdx.x & 31;
    if (lane == 0) sred[warp] = v;
    __syncthreads();
    float t = 0.f;
#pragma unroll
    for (int w = 0; w < NWARP; w++) t += sred[w];
    return t;
}

// Grid barrier: all GRID blocks co-resident (grid == 148 <= SM count).
__device__ __forceinline__ void grid_barrier() {
    __syncthreads();
    if (threadIdx.x == 0) {
        __threadfence();                       // release my global writes
        volatile unsigned* genp = &g_gen;
        unsigned gen = *genp;
        if (atomicAdd(&g_count, 1u) == GRID - 1) {
            atomicExch(&g_count, 0u);
            __threadfence();
            atomicExch(&g_gen, gen + 1u);      // release
        } else {
            while (*genp == gen) { __nanosleep(32); }
            __threadfence();                   // acquire others' writes
        }
    }
    __syncthreads();
}

// Block-wide LN over a 1024-float global vector; per-thread 4 outputs.
__device__ __forceinline__ void ln_block(const float* __restrict__ gvec,
                                         const float* __restrict__ w,
                                         const float* __restrict__ b,
                                         float* sred, float out[4]) {
    int t = threadIdx.x;
    float4 xv = ((const float4*)gvec)[t];
    float mu = block_sum256(xv.x + xv.y + xv.z + xv.w, sred) * (1.f / D);
    float xa[4]; *(float4*)xa = xv;
    float da[4], vs = 0.f;
#pragma unroll
    for (int c = 0; c < 4; c++) { da[c] = xa[c] - mu; vs += da[c] * da[c]; }
    float var = block_sum256(vs, sred) * (1.f / D);
    float rstd = rsqrtf(var + 1e-5f);
    float wa[4], ba[4];
    *(float4*)wa = ((const float4*)w)[t];
    *(float4*)ba = ((const float4*)b)[t];
#pragma unroll
    for (int c = 0; c < 4; c++) out[c] = da[c] * rstd * wa[c] + ba[c];
}

// 1024-dot: weights streamed from global, vector from shared.
__device__ __forceinline__ float dot8g(const float4* __restrict__ w4,
                                       const float4* __restrict__ v4, int lane) {
    float s = 0.f;
#pragma unroll
    for (int j = 0; j < 8; j++) {
        float4 a = w4[lane + 32 * j];
        float4 b = v4[lane + 32 * j];
        s = fmaf(a.x, b.x, s); s = fmaf(a.y, b.y, s);
        s = fmaf(a.z, b.z, s); s = fmaf(a.w, b.w, s);
    }
    return s;
}

// 1024-dot: weights from preloaded registers.
__device__ __forceinline__ float dot8p(const float4* pre,
                                       const float4* __restrict__ v4, int lane) {
    float s = 0.f;
#pragma unroll
    for (int j = 0; j < 8; j++) {
        float4 b = v4[lane + 32 * j];
        s = fmaf(pre[j].x, b.x, s); s = fmaf(pre[j].y, b.y, s);
        s = fmaf(pre[j].z, b.z, s); s = fmaf(pre[j].w, b.w, s);
    }
    return s;
}

__global__ __launch_bounds__(NTH, 1) void rwkv_fused(
    const int* __restrict__ token, const float* __restrict__ state,
    const float* __restrict__ emb,
    const float* __restrict__ ln0_w, const float* __restrict__ ln0_b,
    const float* __restrict__ ln1_w, const float* __restrict__ ln1_b,
    const float* __restrict__ ln2_w, const float* __restrict__ ln2_b,
    const float* __restrict__ kw, const float* __restrict__ vw,
    const float* __restrict__ rw, const float* __restrict__ ow,
    const float* __restrict__ mk, const float* __restrict__ mv,
    const float* __restrict__ mr,
    const float* __restrict__ tf, const float* __restrict__ td,
    const float* __restrict__ fkw, const float* __restrict__ fvw,
    const float* __restrict__ frw,
    const float* __restrict__ fmk, const float* __restrict__ fmr,
    const float* __restrict__ lnw, const float* __restrict__ lnb,
    const float* __restrict__ head,
    float* __restrict__ logits, float* __restrict__ state_out) {
    __shared__ float sred[NWARP];
    __shared__ float s_buf[HD];   // 16KB, reused per phase

    const int t = threadIdx.x, warp = t >> 5, lane = t & 31, bid = blockIdx.x;
    const int wgid = bid * NWARP + warp;
    const bool act128 = (bid < 128);
    const int row = wgid;            // row id for phases A/B/D (valid when act128)

    // ---- embed: block 0 computes g_x = LN0(emb[token]) ----
    if (bid == 0) {
        float4 xv = ((const float4*)(emb + (size_t)token[0] * D))[t];
        float mu = block_sum256(xv.x + xv.y + xv.z + xv.w, sred) * (1.f / D);
        float dx = xv.x - mu, dy = xv.y - mu, dz = xv.z - mu, dw = xv.w - mu;
        float var = block_sum256(dx * dx + dy * dy + dz * dz + dw * dw, sred) * (1.f / D);
        float rstd = rsqrtf(var + 1e-5f);
        float4 wv = ((const float4*)ln0_w)[t];
        float4 bv = ((const float4*)ln0_b)[t];
        float4 o;
        o.x = dx * rstd * wv.x + bv.x;
        o.y = dy * rstd * wv.y + bv.y;
        o.z = dz * rstd * wv.z + bv.z;
        o.w = dw * rstd * wv.w + bv.w;
        ((float4*)g_x)[t] = o;
    }

    float4 pre[8];

    for (int l = 0; l < NL; l++) {
        const size_t lo = (size_t)l * D;
        const size_t sb = (size_t)l * 5 * D;

        // ================= Phase A: time mixing =================
        if (act128) {
            const float4* kr = (const float4*)(kw + lo * D + (size_t)row * D);
#pragma unroll
            for (int j = 0; j < 8; j++) pre[j] = kr[lane + 32 * j];
        }
        grid_barrier();   // g_x final (from embed / previous layer's D)
        if (act128) {
            float xn4[4];
            ln_block(g_x, ln1_w + lo, ln1_b + lo, sred, xn4);
            float mka[4], mva[4], mra[4], sxa[4];
            *(float4*)mka = ((const float4*)(mk + lo))[t];
            *(float4*)mva = ((const float4*)(mv + lo))[t];
            *(float4*)mra = ((const float4*)(mr + lo))[t];
            *(float4*)sxa = ((const float4*)(state + sb + D))[t];  // sx_att
            int base = 4 * t;
#pragma unroll
            for (int c = 0; c < 4; c++) {
                float xn = xn4[c];
                s_buf[base + c]         = xn * mka[c] + sxa[c] * (1.f - mka[c]);
                s_buf[D + base + c]     = xn * mva[c] + sxa[c] * (1.f - mva[c]);
                s_buf[2 * D + base + c] = xn * mra[c] + sxa[c] * (1.f - mra[c]);
                if (bid == 0) state_out[sb + D + base + c] = xn;   // state row 1
            }
            __syncthreads();

            const float4* xk4 = (const float4*)s_buf;
            const float4* xv4 = (const float4*)(s_buf + D);
            const float4* xr4 = (const float4*)(s_buf + 2 * D);
            float sk = dot8p(pre, xk4, lane);
            float sv = dot8g((const float4*)(vw + lo * D + (size_t)row * D), xv4, lane);
            float sr = dot8g((const float4*)(rw + lo * D + (size_t)row * D), xr4, lane);
            sk = warp_sum(sk); sv = warp_sum(sv); sr = warp_sum(sr);

            if (lane == 0) {
                float aa = state[sb + 2 * D + row];
                float bb = state[sb + 3 * D + row];
                float pp = state[sb + 4 * D + row];
                float tfv = tf[lo + row];
                float tdv = td[lo + row];
                float k = sk, v = sv;
                float rs = 1.f / (1.f + expf(-sr));

                float ww = tfv + k;
                float qq = fmaxf(pp, ww);
                float e1 = expf(pp - qq);
                float e2 = expf(ww - qq);
                g_rwkv[row] = rs * (e1 * aa + e2 * v) / (e1 * bb + e2);

                float ww2 = pp + tdv;
                float qq2 = fmaxf(ww2, k);
                float e1b = expf(ww2 - qq2);
                float e2b = expf(k - qq2);
                state_out[sb + 2 * D + row] = e1b * aa + e2b * v;  // aa2
                state_out[sb + 3 * D + row] = e1b * bb + e2b;      // bb2
                state_out[sb + 4 * D + row] = qq2;                 // qq2
            }
        }

        // ================= Phase B: x += ow @ rwkv =================
        if (act128) {
            const float4* orow = (const float4*)(ow + lo * D + (size_t)row * D);
#pragma unroll
            for (int j = 0; j < 8; j++) pre[j] = orow[lane + 32 * j];
        }
        grid_barrier();   // g_rwkv complete
        if (act128) {
            ((float4*)s_buf)[t] = ((const float4*)g_rwkv)[t];
            __syncthreads();
            float s = warp_sum(dot8p(pre, (const float4*)s_buf, lane));
            if (lane == 0) g_x[row] += s;
        }

        // ================= Phase C: channel mix 1 =================
        {   // first unit = wgid < 1184 < HD: always an fkw row
            const float4* wr0 = (const float4*)(fkw + (size_t)l * HD * D + (size_t)wgid * D);
#pragma unroll
            for (int j = 0; j < 8; j++) pre[j] = wr0[lane + 32 * j];
        }
        grid_barrier();   // g_x updated by phase B
        {
            float xn4[4];
            ln_block(g_x, ln2_w + lo, ln2_b + lo, sred, xn4);
            float mka[4], mra[4], sxa[4];
            *(float4*)mka = ((const float4*)(fmk + lo))[t];
            *(float4*)mra = ((const float4*)(fmr + lo))[t];
            *(float4*)sxa = ((const float4*)(state + sb))[t];      // sx_ffn
            int base = 4 * t;
#pragma unroll
            for (int c = 0; c < 4; c++) {
                float xn = xn4[c];
                s_buf[base + c]     = xn * mka[c] + sxa[c] * (1.f - mka[c]);
                s_buf[D + base + c] = xn * mra[c] + sxa[c] * (1.f - mra[c]);
                if (bid == 0) state_out[sb + base + c] = xn;       // state row 0
            }
            __syncthreads();

            // peeled first unit (fkw row wgid) from preloaded regs
            {
                float s = warp_sum(dot8p(pre, (const float4*)s_buf, lane));
                if (lane == 0) { float rl = fmaxf(s, 0.f); g_kk[wgid] = rl * rl; }
            }
            for (int u = wgid + TOTW; u < HD + D; u += TOTW) {
                if (u < HD) {
                    float s = warp_sum(dot8g(
                        (const float4*)(fkw + (size_t)l * HD * D + (size_t)u * D),
                        (const float4*)s_buf, lane));
                    if (lane == 0) { float rl = fmaxf(s, 0.f); g_kk[u] = rl * rl; }
                } else {
                    float s = warp_sum(dot8g(
                        (const float4*)(frw + lo * D + (size_t)(u - HD) * D),
                        (const float4*)(s_buf + D), lane));
                    if (lane == 0) g_r2[u - HD] = 1.f / (1.f + expf(-s));
                }
            }
        }

        // ================= Phase D: x += r2 * (fvw @ kk) =================
        if (act128) {
            const float4* w4 = (const float4*)(fvw + (size_t)l * D * HD + (size_t)row * HD);
#pragma unroll
            for (int j = 0; j < 8; j++) pre[j] = w4[lane + 32 * j];   // first 1/4 of row
        }
        grid_barrier();   // g_kk, g_r2 complete
        if (act128) {
#pragma unroll
            for (int j = 0; j < 4; j++)
                ((float4*)s_buf)[t + NTH * j] = ((const float4*)g_kk)[t + NTH * j];
            __syncthreads();
            const float4* k4 = (const float4*)s_buf;
            float s = dot8p(pre, k4, lane);  // chunk 0
            const float4* w4 = (const float4*)(fvw + (size_t)l * D * HD + (size_t)row * HD);
#pragma unroll
            for (int c = 1; c < 4; c++) {
#pragma unroll
                for (int j = 0; j < 8; j++) {
                    float4 a = w4[c * 256 + lane + 32 * j];
                    float4 b = k4[c * 256 + lane + 32 * j];
                    s = fmaf(a.x, b.x, s); s = fmaf(a.y, b.y, s);
                    s = fmaf(a.z, b.z, s); s = fmaf(a.w, b.w, s);
                }
            }
            s = warp_sum(s);
            if (lane == 0) g_x[row] += g_r2[row] * s;
        }
    }

    // ================= Head: logits = head @ LN(x) =================
    {
        const float4* hr = (const float4*)(head + (size_t)wgid * D);  // wgid < NV
#pragma unroll
        for (int j = 0; j < 8; j++) pre[j] = hr[lane + 32 * j];
    }
    grid_barrier();   // g_x final
    {
        float xn4[4];
        ln_block(g_x, lnw, lnb, sred, xn4);
        int base = 4 * t;
#pragma unroll
        for (int c = 0; c < 4; c++) s_buf[base + c] = xn4[c];
        __syncthreads();

        // peeled first row
        {
            float s = warp_sum(dot8p(pre, (const float4*)s_buf, lane));
            if (lane == 0) logits[wgid] = s;
        }
        for (int v = wgid + TOTW; v < NV; v += TOTW) {
            float s = warp_sum(dot8g((const float4*)(head + (size_t)v * D),
                                     (const float4*)s_buf, lane));
            if (lane == 0) logits[v] = s;
        }
    }
}

// ---------------------------------------------------------------------------
extern "C" void kernel_launch(void* const* d_in, const int* in_sizes, int n_in,
                              void* d_out, int out_size) {
    const int*   token     = (const int*)d_in[0];
    const float* state     = (const float*)d_in[1];
    const float* emb       = (const float*)d_in[2];
    const float* ln0_w     = (const float*)d_in[3];
    const float* ln0_b     = (const float*)d_in[4];
    const float* ln1_w     = (const float*)d_in[5];
    const float* ln1_b     = (const float*)d_in[6];
    const float* ln2_w     = (const float*)d_in[7];
    const float* ln2_b     = (const float*)d_in[8];
    const float* att_key   = (const float*)d_in[9];
    const float* att_value = (const float*)d_in[10];
    const float* att_recep = (const float*)d_in[11];
    const float* att_out   = (const float*)d_in[12];
    const float* tm_k      = (const float*)d_in[13];
    const float* tm_v      = (const float*)d_in[14];
    const float* tm_r      = (const float*)d_in[15];
    const float* t_first   = (const float*)d_in[16];
    const float* t_decay   = (const float*)d_in[17];
    const float* ffn_key   = (const float*)d_in[18];
    const float* ffn_value = (const float*)d_in[19];
    const float* ffn_recep = (const float*)d_in[20];
    const float* ffn_tm_k  = (const float*)d_in[21];
    const float* ffn_tm_r  = (const float*)d_in[22];
    const float* lnout_w   = (const float*)d_in[23];
    const float* lnout_b   = (const float*)d_in[24];
    const float* head      = (const float*)d_in[25];

    float* out = (float*)d_out;
    float* logits = out;
    float* state_out;
    if (out_size >= NV + NL * 5 * D) {
        state_out = out + NV;
    } else {
        void* p = nullptr;
        cudaGetSymbolAddress(&p, g_state_scratch);
        state_out = (float*)p;
    }

    rwkv_fused<<<GRID, NTH>>>(token, state, emb, ln0_w, ln0_b,
                              ln1_w, ln1_b, ln2_w, ln2_b,
                              att_key, att_value, att_recep, att_out,
                              tm_k, tm_v, tm_r, t_first, t_decay,
                              ffn_key, ffn_value, ffn_recep,
                              ffn_tm_k, ffn_tm_r,
                              lnout_w, lnout_b, head,
                              logits, state_out);
}